// round 16
// baseline (speedup 1.0000x reference)
#include <cuda_runtime.h>
#include <cuda_fp16.h>
#include <cstdint>
#include <math.h>

namespace {
constexpr int B  = 128;
constexpr int T  = 512;
constexpr int A  = 256;
constexpr int UG = 512;
constexpr int ROWS = B * T;       // 65536
constexpr int XK = 768;           // x feature width
constexpr int XN = 1536;          // 3 * UG
}

// ---------------- scratch (device globals; no allocation allowed) ------------
__device__ __half g_xh[(size_t)ROWS * XK];      // fp16 x
__device__ __half g_bh[(size_t)XN * XK];        // gru_k^T [N,K] fp16
__device__ __half g_rh[(size_t)XN * UG];        // gru_rk^T [1536,512] fp16
__device__ float g_xp[(size_t)ROWS * XN];       // x @ gru_k + gru_b[0]
__device__ float g_h0f[B * UG];                 // h0 fp32 / final h
__device__ __half g_hh[2][B * UG];              // h ping-pong, fp16 hi
__device__ __half g_hl[2][B * UG];              // h ping-pong, fp16 lo
__device__ float g_hmax[B * UG];
__device__ unsigned g_flag[8][32];              // per-btile arrival flags (16 slots + pad)
__device__ unsigned g_tcnt[T];                  // completed xp n-tiles per timestep

__device__ __forceinline__ float eluf(float v) { return v > 0.f ? v : (expf(v) - 1.f); }
__device__ __forceinline__ void split_f16(float v, __half& h, __half& l) {
    h = __float2half(v);
    l = __float2half(v - __half2float(h));
}
// fast activations (MUFU)
__device__ __forceinline__ float ftanh(float v) {
    float r;
    asm("tanh.approx.f32 %0, %1;" : "=f"(r) : "f"(v));
    return r;
}
__device__ __forceinline__ float fsigm(float v) {
    float p, r;
    asm("ex2.approx.f32 %0, %1;" : "=f"(p) : "f"(-1.4426950408889634f * v));
    asm("rcp.approx.f32 %0, %1;" : "=f"(r) : "f"(1.f + p));
    return r;
}

// ---------------- PTX helpers (plain sm_103-safe) -----------------------------
__device__ __forceinline__ uint32_t smem_u32(const void* p) {
    uint32_t a;
    asm("{ .reg .u64 t; cvta.to.shared.u64 t, %1; cvt.u32.u64 %0, t; }" : "=r"(a) : "l"(p));
    return a;
}
__device__ __forceinline__ void cpa16(uint32_t s, const void* g) {
    asm volatile("cp.async.cg.shared.global [%0], [%1], 16;" :: "r"(s), "l"(g));
}
__device__ __forceinline__ void ldm4(uint32_t* r, uint32_t a) {
    asm volatile("ldmatrix.sync.aligned.m8n8.x4.shared.b16 {%0,%1,%2,%3}, [%4];"
                 : "=r"(r[0]), "=r"(r[1]), "=r"(r[2]), "=r"(r[3]) : "r"(a));
}
__device__ __forceinline__ void mma16816(float* c, const uint32_t* a, uint32_t b0, uint32_t b1) {
    asm volatile(
        "mma.sync.aligned.m16n8k16.row.col.f32.f16.f16.f32 "
        "{%0,%1,%2,%3}, {%4,%5,%6,%7}, {%8,%9}, {%0,%1,%2,%3};"
        : "+f"(c[0]), "+f"(c[1]), "+f"(c[2]), "+f"(c[3])
        : "r"(a[0]), "r"(a[1]), "r"(a[2]), "r"(a[3]), "r"(b0), "r"(b1));
}
__device__ __forceinline__ unsigned atomAddRel(unsigned* p, unsigned v) {
    unsigned o;
    asm volatile("atom.release.gpu.global.add.u32 %0, [%1], %2;"
                 : "=r"(o) : "l"(p), "r"(v) : "memory");
    return o;
}
__device__ __forceinline__ void stRel(unsigned* p, unsigned v) {
    asm volatile("st.release.gpu.global.u32 [%0], %1;" :: "l"(p), "r"(v) : "memory");
}
__device__ __forceinline__ unsigned ldAcq(unsigned* p) {
    unsigned v;
    asm volatile("ld.acquire.gpu.global.u32 %0, [%1];" : "=r"(v) : "l"(p) : "memory");
    return v;
}
#define BARNAMED(id, cnt) asm volatile("bar.sync %0, %1;" :: "r"(id), "r"(cnt) : "memory")

// ---------------- front-end kernels -------------------------------------------
__global__ void k_reset() {
    int i = threadIdx.x; // 512
    g_tcnt[i] = 0;
    if (i < 256) ((unsigned*)g_flag)[i] = 0;
}

// fused msrs + h0
__global__ void k_init(const float* __restrict__ motion, const float* __restrict__ robot,
                       const float* __restrict__ state,
                       const float* __restrict__ Wm, const float* __restrict__ bm,
                       const float* __restrict__ Wr, const float* __restrict__ br,
                       const float* __restrict__ Wc, const float* __restrict__ bc) {
    int b = blockIdx.x;
    int tid = threadIdx.x; // 512
    __shared__ float inbuf[128];
    __shared__ float s[1024];
    if (tid < 64) inbuf[tid] = motion[b * 64 + tid];
    else if (tid < 128) inbuf[tid] = robot[b * 64 + (tid - 64)];
    s[512 + tid] = state[b * 512 + tid];
    __syncthreads();
    {
        int half = tid >> 8;
        int j = tid & 255;
        const float* W = half ? Wr : Wm;
        const float* bb = half ? br : bm;
        const float* in = inbuf + half * 64;
        float acc = bb[j];
        for (int k = 0; k < 64; k++) acc += in[k] * W[k * 256 + j];
        s[half * 256 + j] = eluf(acc);
    }
    __syncthreads();
    float acc = bc[tid];
    for (int k = 0; k < 1024; k++) acc += s[k] * Wc[k * 512 + tid];
    float h0 = eluf(acc);
    size_t idx = (size_t)b * 512 + tid;
    g_h0f[idx] = h0;
    split_f16(h0, g_hh[0][idx], g_hl[0][idx]);
}

// fused act + inp2 + inp3
__global__ void k_front(const float* __restrict__ action, const float* __restrict__ mu,
                        const float* __restrict__ mean, const float* __restrict__ osc,
                        const float* __restrict__ W2, const float* __restrict__ b2,
                        const float* __restrict__ W3, const float* __restrict__ b3) {
    int r0 = blockIdx.x * 8;
    int j = threadIdx.x; // 256
    __shared__ float sin_[8][64];
    __shared__ float smid[8][256];
#pragma unroll
    for (int i = 0; i < 8; i++) {
        int r = r0 + i;
        int t = r >> 7, b = r & 127;
        float v = action[((size_t)b * T + t) * A + j] * mu[b * A + j] + mean[b * A + j];
        g_xh[(size_t)r * XK + j] = __float2half(v);
    }
    for (int i = threadIdx.x; i < 8 * 64; i += 256) {
        int rr = i >> 6, k = i & 63;
        int r = r0 + rr;
        int t = r >> 7, b = r & 127;
        sin_[rr][k] = osc[((size_t)b * T + t) * 128 + k];
    }
    __syncthreads();
    {
        float bj = b2[j];
        float acc[8];
#pragma unroll
        for (int i = 0; i < 8; i++) acc[i] = bj;
        for (int k = 0; k < 64; k++) {
            float w = W2[k * 256 + j];
#pragma unroll
            for (int i = 0; i < 8; i++) acc[i] += sin_[i][k] * w;
        }
#pragma unroll
        for (int i = 0; i < 8; i++) {
            float v = eluf(acc[i]);
            smid[i][j] = v;
            g_xh[(size_t)(r0 + i) * XK + 256 + j] = __float2half(v);
        }
    }
    __syncthreads();
    {
        float bj = b3[j];
        float acc[8];
#pragma unroll
        for (int i = 0; i < 8; i++) acc[i] = bj;
        for (int k = 0; k < 192; k++) {
            float w = W3[k * 256 + j];
#pragma unroll
            for (int i = 0; i < 8; i++) acc[i] += smid[i][64 + k] * w;
        }
#pragma unroll
        for (int i = 0; i < 8; i++)
            g_xh[(size_t)(r0 + i) * XK + 512 + j] = __float2half(eluf(acc[i]));
    }
}

// transpose gru_k [768,1536] -> g_bh [1536,768] fp16
__global__ void k_trb(const float* __restrict__ gk) {
    __shared__ float s[32][33];
    int n0 = blockIdx.x * 32, k0 = blockIdx.y * 32;
    int tx = threadIdx.x, ty = threadIdx.y;
#pragma unroll
    for (int i = 0; i < 32; i += 8)
        s[ty + i][tx] = gk[(size_t)(k0 + ty + i) * XN + n0 + tx];
    __syncthreads();
#pragma unroll
    for (int i = 0; i < 32; i += 8) {
        size_t idx = (size_t)(n0 + ty + i) * XK + k0 + tx;
        g_bh[idx] = __float2half(s[tx][ty + i]);
    }
}

// transpose gru_rk [512,1536] -> g_rh [1536,512] fp16
__global__ void k_trw(const float* __restrict__ wr) {
    __shared__ float s[32][33];
    int n0 = blockIdx.x * 32, k0 = blockIdx.y * 32;
    int tx = threadIdx.x, ty = threadIdx.y;
#pragma unroll
    for (int i = 0; i < 32; i += 8)
        s[ty + i][tx] = wr[(size_t)(k0 + ty + i) * XN + n0 + tx];
    __syncthreads();
#pragma unroll
    for (int i = 0; i < 32; i += 8) {
        size_t idx = (size_t)(n0 + ty + i) * UG + k0 + tx;
        g_rh[idx] = __float2half(s[tx][ty + i]);
    }
}

// ---------------- FUSED persistent kernel -------------------------------------
namespace {
constexpr int PITCHB = 80;
constexpr int ARRB   = 128 * PITCHB;       // 10240
constexpr int BUFB   = 2 * ARRB;           // 20480 : A | B
constexpr int PROD_BYTES = 3 * BUFB;       // 61440
constexpr int KCH = 24;
constexpr int NJOBS = T * (XN / 128);      // 6144, 12 per t
constexpr int PITCH = 1040;
constexpr int WSEC  = 32 * PITCH;              // 33280 per gate (32 u rows)
constexpr int W_OFF = PROD_BYTES;              // 61440
constexpr int AHI_OFF = W_OFF + 3 * WSEC;      // 161280
constexpr int ALO_OFF = AHI_OFF + 16 * PITCH;  // 177920
constexpr int SMEM_FUSED = ALO_OFF + 16 * PITCH; // 194560
}

__global__ void __launch_bounds__(384, 1) k_fused(const float* __restrict__ gb) {
    extern __shared__ char smem[];
    const uint32_t sb = smem_u32(smem);
    const int tid = threadIdx.x;

    if (tid < 256) {
        // ================= PRODUCTION (1-term fp16) =================
        const int lane = tid & 31, wid = tid >> 5;
        const int wm = wid & 3;
        const int wn = wid >> 2;
        const uint32_t aAddr = sb + (wm * 32 + (lane & 15)) * PITCHB + (lane >> 4) * 16;
        const uint32_t bAddr = sb + ARRB + (wn * 64 + (lane & 15)) * PITCHB + (lane >> 4) * 16;

        for (int job = blockIdx.x; job < NJOBS; job += 128) {
            const int t = job / 12, nt = job % 12;
            const int m0 = t * 128;
            const int n0 = nt * 128;
            const __half* gp0 = g_xh + (size_t)m0 * XK;
            const __half* gp1 = g_bh + (size_t)n0 * XK;

            auto load_chunk = [&](int c, int buf) {
                uint32_t base = sb + buf * BUFB;
#pragma unroll
                for (int l = 0; l < 4; l++) {
                    int idx = tid + 256 * l;
                    int arr = idx >> 9;
                    int rem = idx & 511;
                    int row = rem >> 2;
                    int cch = rem & 3;
                    const __half* g = arr ? gp1 : gp0;
                    cpa16(base + arr * ARRB + row * PITCHB + cch * 16,
                          g + (size_t)row * XK + c * 32 + cch * 8);
                }
                asm volatile("cp.async.commit_group;" ::: "memory");
            };

            float acc[2][8][4];
#pragma unroll
            for (int i = 0; i < 2; i++)
#pragma unroll
                for (int jj = 0; jj < 8; jj++)
#pragma unroll
                    for (int q = 0; q < 4; q++) acc[i][jj][q] = 0.f;

            load_chunk(0, 0);
            load_chunk(1, 1);

            for (int c = 0; c < KCH; c++) {
                if (c + 1 < KCH) asm volatile("cp.async.wait_group 1;" ::: "memory");
                else             asm volatile("cp.async.wait_group 0;" ::: "memory");
                BARNAMED(2, 256);
                if (c + 2 < KCH) load_chunk(c + 2, (c + 2) % 3);

                uint32_t boff = (c % 3) * BUFB;
#pragma unroll
                for (int ks = 0; ks < 2; ks++) {
                    uint32_t ah[2][4], bh[4][4];
#pragma unroll
                    for (int mt = 0; mt < 2; mt++)
                        ldm4(ah[mt], aAddr + boff + mt * (16 * PITCHB) + ks * 32);
#pragma unroll
                    for (int ng = 0; ng < 4; ng++)
                        ldm4(bh[ng], bAddr + boff + ng * (16 * PITCHB) + ks * 32);
#pragma unroll
                    for (int mt = 0; mt < 2; mt++)
#pragma unroll
                        for (int ng = 0; ng < 4; ng++)
#pragma unroll
                            for (int hf = 0; hf < 2; hf++)
                                mma16816(acc[mt][ng * 2 + hf], ah[mt],
                                         bh[ng][hf], bh[ng][hf + 2]);
                }
            }

            const int qr = lane >> 2, qc = lane & 3;
#pragma unroll
            for (int mt = 0; mt < 2; mt++)
#pragma unroll
                for (int ntl = 0; ntl < 8; ntl++) {
                    int nb = n0 + wn * 64 + ntl * 8 + 2 * qc;
                    float b0 = gb[nb], b1 = gb[nb + 1];
#pragma unroll
                    for (int rp = 0; rp < 2; rp++) {
                        int m = m0 + wm * 32 + mt * 16 + qr + 8 * rp;
                        float2 v = make_float2(acc[mt][ntl][2 * rp] + b0,
                                               acc[mt][ntl][2 * rp + 1] + b1);
                        *(float2*)&g_xp[(size_t)m * XN + nb] = v;
                    }
                }

            BARNAMED(2, 256);
            if (tid == 0) atomAddRel(&g_tcnt[t], 1u);
        }
    } else {
        // ================= RECURRENCE (16 b x 32 u per block) =================
        const int ltid = tid - 256;
        const int lane = ltid & 31, lwid = ltid >> 5;  // 4 warps
        const int uh = lwid;
        const int bt = blockIdx.x & 7;
        const int ut = blockIdx.x >> 3;                // slot in flag array
        const int u0 = ut * 32;
        const int row0 = bt * 16;
        const int qr = lane >> 2, qc = lane & 3;
        const int r1 = row0 + qr;
        const int r2 = r1 + 8;
        const int uc = u0 + uh * 8 + 2 * qc;

        for (int idx = ltid; idx < 6144; idx += 128) {
            int sec = idx >> 11;
            int rem = idx & 2047;
            int r = rem >> 6, ch = rem & 63;
            cpa16(sb + W_OFF + sec * WSEC + r * PITCH + ch * 16,
                  g_rh + ((size_t)(sec * 512 + u0 + r)) * UG + ch * 8);
        }
        asm volatile("cp.async.commit_group;" ::: "memory");

        const float* gbr = gb + XN;
        float bzc[2], brc[2], bhc[2];
#pragma unroll
        for (int j = 0; j < 2; j++) {
            bzc[j] = gbr[uc + j];
            brc[j] = gbr[512 + uc + j];
            bhc[j] = gbr[1024 + uc + j];
        }

        float hprev[4], hmax[4];
        hprev[0] = g_h0f[(size_t)r1 * UG + uc];
        hprev[1] = g_h0f[(size_t)r1 * UG + uc + 1];
        hprev[2] = g_h0f[(size_t)r2 * UG + uc];
        hprev[3] = g_h0f[(size_t)r2 * UG + uc + 1];
#pragma unroll
        for (int i = 0; i < 4; i++) hmax[i] = -INFINITY;

        const uint32_t aHi = sb + AHI_OFF + (lane & 15) * PITCH + ((lane >> 4) & 1) * 16;
        const uint32_t aLo = aHi + 16 * PITCH;
        uint32_t bHi[3];
        {
            int brow = uh * 8 + (lane & 7);
            int bch = lane >> 3;
#pragma unroll
            for (int g = 0; g < 3; g++)
                bHi[g] = sb + W_OFF + g * WSEC + brow * PITCH + bch * 16;
        }

        auto stageA = [&](int par) {
            const __half* shp = g_hh[par] + (size_t)row0 * UG;
            const __half* slp = g_hl[par] + (size_t)row0 * UG;
#pragma unroll
            for (int kh = 0; kh < 2; kh++) {
                for (int idx = ltid; idx < 512; idx += 128) {
                    int r = idx >> 5, ch = (idx & 31) + kh * 32;
                    cpa16(sb + AHI_OFF + r * PITCH + ch * 16, shp + (size_t)r * UG + ch * 8);
                    cpa16(sb + ALO_OFF + r * PITCH + ch * 16, slp + (size_t)r * UG + ch * 8);
                }
                asm volatile("cp.async.commit_group;" ::: "memory");
            }
        };

        stageA(0);

        {
            int spins = 0;
            while (ldAcq(&g_tcnt[0]) < 12u) {
                if (++spins > 16) asm volatile("nanosleep.u32 128;");
            }
        }
        float2 xz[2], xr[2], xh[2];
        {
            const float* xpr1 = g_xp + (size_t)r1 * XN;
            const float* xpr2 = g_xp + (size_t)r2 * XN;
            xz[0] = *(const float2*)(xpr1 + uc);        xz[1] = *(const float2*)(xpr2 + uc);
            xr[0] = *(const float2*)(xpr1 + 512 + uc);  xr[1] = *(const float2*)(xpr2 + 512 + uc);
            xh[0] = *(const float2*)(xpr1 + 1024 + uc); xh[1] = *(const float2*)(xpr2 + 1024 + uc);
        }

        unsigned* flags = &g_flag[bt][0];

        for (int t = 0; t < T; t++) {
            // 8 independent accumulator sets — max chain depth 16
            float az[4] = {0, 0, 0, 0}, azB[4] = {0, 0, 0, 0};
            float ar[4] = {0, 0, 0, 0}, arB[4] = {0, 0, 0, 0};
            float ahA[4] = {0, 0, 0, 0}, ahBv[4] = {0, 0, 0, 0};
            float ahC[4] = {0, 0, 0, 0}, ahD[4] = {0, 0, 0, 0};

            // first k-half
            asm volatile("cp.async.wait_group 1;" ::: "memory");
            BARNAMED(1, 128);
#pragma unroll 4
            for (int j = 0; j < 8; j++) {
                uint32_t ah0[4], ah1[4], al0[4], al1[4];
                uint32_t a = aHi + j * 64;
                ldm4(ah0, a);
                ldm4(ah1, a + 32);
                uint32_t al = aLo + j * 64;
                ldm4(al0, al);
                ldm4(al1, al + 32);
                uint32_t b4h[4];
                ldm4(b4h, bHi[0] + j * 64);
                mma16816(az,  ah0, b4h[0], b4h[1]);
                mma16816(azB, ah1, b4h[2], b4h[3]);
                ldm4(b4h, bHi[1] + j * 64);
                mma16816(ar,  ah0, b4h[0], b4h[1]);
                mma16816(arB, ah1, b4h[2], b4h[3]);
                ldm4(b4h, bHi[2] + j * 64);
                mma16816(ahA,  ah0, b4h[0], b4h[1]);
                mma16816(ahBv, al0, b4h[0], b4h[1]);
                mma16816(ahC,  ah1, b4h[2], b4h[3]);
                mma16816(ahD,  al1, b4h[2], b4h[3]);
            }
            // second k-half
            asm volatile("cp.async.wait_group 0;" ::: "memory");
            BARNAMED(1, 128);
#pragma unroll 4
            for (int j = 8; j < 16; j++) {
                uint32_t ah0[4], ah1[4], al0[4], al1[4];
                uint32_t a = aHi + j * 64;
                ldm4(ah0, a);
                ldm4(ah1, a + 32);
                uint32_t al = aLo + j * 64;
                ldm4(al0, al);
                ldm4(al1, al + 32);
                uint32_t b4h[4];
                ldm4(b4h, bHi[0] + j * 64);
                mma16816(az,  ah0, b4h[0], b4h[1]);
                mma16816(azB, ah1, b4h[2], b4h[3]);
                ldm4(b4h, bHi[1] + j * 64);
                mma16816(ar,  ah0, b4h[0], b4h[1]);
                mma16816(arB, ah1, b4h[2], b4h[3]);
                ldm4(b4h, bHi[2] + j * 64);
                mma16816(ahA,  ah0, b4h[0], b4h[1]);
                mma16816(ahBv, al0, b4h[0], b4h[1]);
                mma16816(ahC,  ah1, b4h[2], b4h[3]);
                mma16816(ahD,  al1, b4h[2], b4h[3]);
            }

#pragma unroll
            for (int i = 0; i < 4; i++) {
                az[i] += azB[i];
                ar[i] += arB[i];
                ahA[i] = (ahA[i] + ahBv[i]) + (ahC[i] + ahD[i]);
            }

            int np = (t + 1) & 1;
            bool notlast = (t + 1 < T);
#pragma unroll
            for (int pp = 0; pp < 2; pp++) {
                float hn[2];
#pragma unroll
                for (int j = 0; j < 2; j++) {
                    int i = 2 * pp + j;
                    float xzv = j ? xz[pp].y : xz[pp].x;
                    float xrv = j ? xr[pp].y : xr[pp].x;
                    float xhv = j ? xh[pp].y : xh[pp].x;
                    float z = fsigm(xzv + az[i] + bzc[j]);
                    float r = fsigm(xrv + ar[i] + brc[j]);
                    float hc = ftanh(xhv + r * (ahA[i] + bhc[j]));
                    hn[j] = z * hprev[i] + (1.f - z) * hc;
                    hprev[i] = hn[j];
                    hmax[i] = fmaxf(hmax[i], hn[j]);
                }
                if (notlast) {
                    int rowg = pp ? r2 : r1;
                    __half2 vh, vl;
                    __half h0b, l0b, h1b, l1b;
                    split_f16(hn[0], h0b, l0b);
                    split_f16(hn[1], h1b, l1b);
                    vh.x = h0b; vh.y = h1b;
                    vl.x = l0b; vl.y = l1b;
                    *(__half2*)&g_hh[np][(size_t)rowg * UG + uc] = vh;
                    *(__half2*)&g_hl[np][(size_t)rowg * UG + uc] = vl;
                }
            }

            if (notlast) {
                // EARLY ARRIVE: parallel flag-slot publication (no atomic serialize)
                BARNAMED(1, 128);          // h stores complete CTA-wide
                if (ltid == 0) stRel(&flags[ut], (unsigned)(t + 1));
                // overlap: xp(t+1) spin + prefetch while peers arrive
                {
                    int spins = 0;
                    while (ldAcq(&g_tcnt[t + 1]) < 12u) {
                        if (++spins > 16) asm volatile("nanosleep.u32 128;");
                    }
                }
                {
                    const float* xp = g_xp + (size_t)(t + 1) * ((size_t)B * XN);
                    const float* xpr1 = xp + (size_t)r1 * XN;
                    const float* xpr2 = xp + (size_t)r2 * XN;
                    xz[0] = *(const float2*)(xpr1 + uc);        xz[1] = *(const float2*)(xpr2 + uc);
                    xr[0] = *(const float2*)(xpr1 + 512 + uc);  xr[1] = *(const float2*)(xpr2 + 512 + uc);
                    xh[0] = *(const float2*)(xpr1 + 1024 + uc); xh[1] = *(const float2*)(xpr2 + 1024 + uc);
                }
                // vote-based flag poll: lane polls slot (lane & 15)
                {
                    unsigned tgt = (unsigned)(t + 1);
                    unsigned* fp = flags + (lane & 15);
                    int spins = 0;
                    for (;;) {
                        unsigned v = ldAcq(fp);
                        if (__all_sync(0xFFFFFFFFu, v >= tgt)) break;
                        if (++spins > 48) asm volatile("nanosleep.u32 32;");
                    }
                }
                stageA(np);
            }
        }

        float2 v;
        v.x = hmax[0]; v.y = hmax[1]; *(float2*)&g_hmax[(size_t)r1 * UG + uc] = v;
        v.x = hmax[2]; v.y = hmax[3]; *(float2*)&g_hmax[(size_t)r2 * UG + uc] = v;
        v.x = hprev[0]; v.y = hprev[1]; *(float2*)&g_h0f[(size_t)r1 * UG + uc] = v;
        v.x = hprev[2]; v.y = hprev[3]; *(float2*)&g_h0f[(size_t)r2 * UG + uc] = v;
    }
}

// ---------------- epilogue ---------------------------------------------------
__global__ void k_out(const float* __restrict__ Wout, const float* __restrict__ bout,
                      float* __restrict__ dout, int out_size) {
    int b = blockIdx.x;
    int tid = threadIdx.x; // 256
    __shared__ float red[256];
    float s = 0.f;
    for (int uu = tid; uu < UG; uu += 256) s += g_hmax[b * UG + uu] * Wout[uu];
    red[tid] = s;
    __syncthreads();
    for (int o = 128; o > 0; o >>= 1) {
        if (tid < o) red[tid] += red[tid + o];
        __syncthreads();
    }
    if (tid == 0 && b < out_size) dout[b] = eluf(red[0] + bout[0]);
    for (int uu = tid; uu < UG; uu += 256) {
        int idx = B + b * UG + uu;
        if (idx < out_size) dout[idx] = g_h0f[b * UG + uu];
    }
}

// ---------------- launch ------------------------------------------------------
extern "C" void kernel_launch(void* const* d_in, const int* in_sizes, int n_in,
                              void* d_out, int out_size) {
    const float* motion = (const float*)d_in[0];
    const float* robot  = (const float*)d_in[1];
    const float* action = (const float*)d_in[3];
    const float* osc    = (const float*)d_in[4];
    const float* mu     = (const float*)d_in[5];
    const float* mean   = (const float*)d_in[6];
    const float* state  = (const float*)d_in[7];
    const float* W_mot  = (const float*)d_in[8];
    const float* b_mot  = (const float*)d_in[9];
    const float* W_rob  = (const float*)d_in[10];
    const float* b_rob  = (const float*)d_in[11];
    const float* W_comb = (const float*)d_in[12];
    const float* b_comb = (const float*)d_in[13];
    const float* W_oscr = (const float*)d_in[14];
    const float* b_oscr = (const float*)d_in[15];
    const float* W_osci = (const float*)d_in[16];
    const float* b_osci = (const float*)d_in[17];
    const float* gru_k  = (const float*)d_in[18];
    const float* gru_rk = (const float*)d_in[19];
    const float* gru_b  = (const float*)d_in[20];
    const float* W_out  = (const float*)d_in[21];
    const float* b_out  = (const float*)d_in[22];
    float* out = (float*)d_out;

    static bool attr_set = false;
    if (!attr_set) {
        cudaFuncSetAttribute(k_fused, cudaFuncAttributeMaxDynamicSharedMemorySize, SMEM_FUSED);
        attr_set = true;
    }

    k_reset<<<1, 512>>>();                                             // 0
    k_init<<<B, 512>>>(motion, robot, state, W_mot, b_mot,
                       W_rob, b_rob, W_comb, b_comb);                  // 1
    k_front<<<ROWS / 8, 256>>>(action, mu, mean, osc,
                               W_oscr, b_oscr, W_osci, b_osci);        // 2
    k_trb<<<dim3(XN / 32, XK / 32), dim3(32, 8)>>>(gru_k);             // 3
    k_trw<<<dim3(XN / 32, UG / 32), dim3(32, 8)>>>(gru_rk);            // 4
    k_fused<<<128, 384, SMEM_FUSED>>>(gru_b);                          // 5
    k_out<<<B, 256>>>(W_out, b_out, out, out_size);                    // 6
}

// round 17
// speedup vs baseline: 1.0516x; 1.0516x over previous
#include <cuda_runtime.h>
#include <cuda_fp16.h>
#include <cstdint>
#include <math.h>

namespace {
constexpr int B  = 128;
constexpr int T  = 512;
constexpr int A  = 256;
constexpr int UG = 512;
constexpr int ROWS = B * T;       // 65536
constexpr int XK = 768;           // x feature width
constexpr int XN = 1536;          // 3 * UG
}

// ---------------- scratch (device globals; no allocation allowed) ------------
__device__ __half g_xh[(size_t)ROWS * XK];      // fp16 x
__device__ __half g_bh[(size_t)XN * XK];        // gru_k^T [N,K] fp16
__device__ __half g_rh[(size_t)XN * UG];        // gru_rk^T [1536,512] fp16
__device__ float g_xp[(size_t)ROWS * XN];       // x @ gru_k + gru_b[0]
__device__ float g_h0f[B * UG];                 // h0 fp32 / final h
__device__ __half g_hh[2][B * UG];              // h ping-pong, fp16 hi
__device__ __half g_hl[2][B * UG];              // h ping-pong, fp16 lo
__device__ float g_hmax[B * UG];
__device__ unsigned g_barp[8][32];              // per-btile barrier arrivals (padded)
__device__ unsigned g_genp[8][32];              // per-btile generation (padded)
__device__ unsigned g_tcnt[T];                  // completed xp n-tiles per timestep

__device__ __forceinline__ float eluf(float v) { return v > 0.f ? v : (expf(v) - 1.f); }
__device__ __forceinline__ void split_f16(float v, __half& h, __half& l) {
    h = __float2half(v);
    l = __float2half(v - __half2float(h));
}
// fast activations (MUFU)
__device__ __forceinline__ float ftanh(float v) {
    float r;
    asm("tanh.approx.f32 %0, %1;" : "=f"(r) : "f"(v));
    return r;
}
__device__ __forceinline__ float fsigm(float v) {
    float p, r;
    asm("ex2.approx.f32 %0, %1;" : "=f"(p) : "f"(-1.4426950408889634f * v));
    asm("rcp.approx.f32 %0, %1;" : "=f"(r) : "f"(1.f + p));
    return r;
}

// ---------------- PTX helpers (plain sm_103-safe) -----------------------------
__device__ __forceinline__ uint32_t smem_u32(const void* p) {
    uint32_t a;
    asm("{ .reg .u64 t; cvta.to.shared.u64 t, %1; cvt.u32.u64 %0, t; }" : "=r"(a) : "l"(p));
    return a;
}
__device__ __forceinline__ void cpa16(uint32_t s, const void* g) {
    asm volatile("cp.async.cg.shared.global [%0], [%1], 16;" :: "r"(s), "l"(g));
}
__device__ __forceinline__ void ldm4(uint32_t* r, uint32_t a) {
    asm volatile("ldmatrix.sync.aligned.m8n8.x4.shared.b16 {%0,%1,%2,%3}, [%4];"
                 : "=r"(r[0]), "=r"(r[1]), "=r"(r[2]), "=r"(r[3]) : "r"(a));
}
__device__ __forceinline__ void mma16816(float* c, const uint32_t* a, uint32_t b0, uint32_t b1) {
    asm volatile(
        "mma.sync.aligned.m16n8k16.row.col.f32.f16.f16.f32 "
        "{%0,%1,%2,%3}, {%4,%5,%6,%7}, {%8,%9}, {%0,%1,%2,%3};"
        : "+f"(c[0]), "+f"(c[1]), "+f"(c[2]), "+f"(c[3])
        : "r"(a[0]), "r"(a[1]), "r"(a[2]), "r"(a[3]), "r"(b0), "r"(b1));
}
__device__ __forceinline__ unsigned atomAddRel(unsigned* p, unsigned v) {
    unsigned o;
    asm volatile("atom.release.gpu.global.add.u32 %0, [%1], %2;"
                 : "=r"(o) : "l"(p), "r"(v) : "memory");
    return o;
}
__device__ __forceinline__ void stRel(unsigned* p, unsigned v) {
    asm volatile("st.release.gpu.global.u32 [%0], %1;" :: "l"(p), "r"(v) : "memory");
}
__device__ __forceinline__ unsigned ldAcq(unsigned* p) {
    unsigned v;
    asm volatile("ld.acquire.gpu.global.u32 %0, [%1];" : "=r"(v) : "l"(p) : "memory");
    return v;
}
#define BARNAMED(id, cnt) asm volatile("bar.sync %0, %1;" :: "r"(id), "r"(cnt) : "memory")

// ---------------- front-end kernels -------------------------------------------
__global__ void k_reset() {
    int i = threadIdx.x; // 512
    g_tcnt[i] = 0;
    if (i < 8) { g_barp[i][0] = 0; g_genp[i][0] = 0; }
}

// fused msrs + h0
__global__ void k_init(const float* __restrict__ motion, const float* __restrict__ robot,
                       const float* __restrict__ state,
                       const float* __restrict__ Wm, const float* __restrict__ bm,
                       const float* __restrict__ Wr, const float* __restrict__ br,
                       const float* __restrict__ Wc, const float* __restrict__ bc) {
    int b = blockIdx.x;
    int tid = threadIdx.x; // 512
    __shared__ float inbuf[128];
    __shared__ float s[1024];
    if (tid < 64) inbuf[tid] = motion[b * 64 + tid];
    else if (tid < 128) inbuf[tid] = robot[b * 64 + (tid - 64)];
    s[512 + tid] = state[b * 512 + tid];
    __syncthreads();
    {
        int half = tid >> 8;
        int j = tid & 255;
        const float* W = half ? Wr : Wm;
        const float* bb = half ? br : bm;
        const float* in = inbuf + half * 64;
        float acc = bb[j];
        for (int k = 0; k < 64; k++) acc += in[k] * W[k * 256 + j];
        s[half * 256 + j] = eluf(acc);
    }
    __syncthreads();
    float acc = bc[tid];
    for (int k = 0; k < 1024; k++) acc += s[k] * Wc[k * 512 + tid];
    float h0 = eluf(acc);
    size_t idx = (size_t)b * 512 + tid;
    g_h0f[idx] = h0;
    split_f16(h0, g_hh[0][idx], g_hl[0][idx]);
}

// fused act + inp2 + inp3
__global__ void k_front(const float* __restrict__ action, const float* __restrict__ mu,
                        const float* __restrict__ mean, const float* __restrict__ osc,
                        const float* __restrict__ W2, const float* __restrict__ b2,
                        const float* __restrict__ W3, const float* __restrict__ b3) {
    int r0 = blockIdx.x * 8;
    int j = threadIdx.x; // 256
    __shared__ float sin_[8][64];
    __shared__ float smid[8][256];
#pragma unroll
    for (int i = 0; i < 8; i++) {
        int r = r0 + i;
        int t = r >> 7, b = r & 127;
        float v = action[((size_t)b * T + t) * A + j] * mu[b * A + j] + mean[b * A + j];
        g_xh[(size_t)r * XK + j] = __float2half(v);
    }
    for (int i = threadIdx.x; i < 8 * 64; i += 256) {
        int rr = i >> 6, k = i & 63;
        int r = r0 + rr;
        int t = r >> 7, b = r & 127;
        sin_[rr][k] = osc[((size_t)b * T + t) * 128 + k];
    }
    __syncthreads();
    {
        float bj = b2[j];
        float acc[8];
#pragma unroll
        for (int i = 0; i < 8; i++) acc[i] = bj;
        for (int k = 0; k < 64; k++) {
            float w = W2[k * 256 + j];
#pragma unroll
            for (int i = 0; i < 8; i++) acc[i] += sin_[i][k] * w;
        }
#pragma unroll
        for (int i = 0; i < 8; i++) {
            float v = eluf(acc[i]);
            smid[i][j] = v;
            g_xh[(size_t)(r0 + i) * XK + 256 + j] = __float2half(v);
        }
    }
    __syncthreads();
    {
        float bj = b3[j];
        float acc[8];
#pragma unroll
        for (int i = 0; i < 8; i++) acc[i] = bj;
        for (int k = 0; k < 192; k++) {
            float w = W3[k * 256 + j];
#pragma unroll
            for (int i = 0; i < 8; i++) acc[i] += smid[i][64 + k] * w;
        }
#pragma unroll
        for (int i = 0; i < 8; i++)
            g_xh[(size_t)(r0 + i) * XK + 512 + j] = __float2half(eluf(acc[i]));
    }
}

// transpose gru_k [768,1536] -> g_bh [1536,768] fp16
__global__ void k_trb(const float* __restrict__ gk) {
    __shared__ float s[32][33];
    int n0 = blockIdx.x * 32, k0 = blockIdx.y * 32;
    int tx = threadIdx.x, ty = threadIdx.y;
#pragma unroll
    for (int i = 0; i < 32; i += 8)
        s[ty + i][tx] = gk[(size_t)(k0 + ty + i) * XN + n0 + tx];
    __syncthreads();
#pragma unroll
    for (int i = 0; i < 32; i += 8) {
        size_t idx = (size_t)(n0 + ty + i) * XK + k0 + tx;
        g_bh[idx] = __float2half(s[tx][ty + i]);
    }
}

// transpose gru_rk [512,1536] -> g_rh [1536,512] fp16
__global__ void k_trw(const float* __restrict__ wr) {
    __shared__ float s[32][33];
    int n0 = blockIdx.x * 32, k0 = blockIdx.y * 32;
    int tx = threadIdx.x, ty = threadIdx.y;
#pragma unroll
    for (int i = 0; i < 32; i += 8)
        s[ty + i][tx] = wr[(size_t)(k0 + ty + i) * XN + n0 + tx];
    __syncthreads();
#pragma unroll
    for (int i = 0; i < 32; i += 8) {
        size_t idx = (size_t)(n0 + ty + i) * UG + k0 + tx;
        g_rh[idx] = __float2half(s[tx][ty + i]);
    }
}

// ---------------- FUSED persistent kernel -------------------------------------
namespace {
constexpr int PITCHB = 80;
constexpr int ARRB   = 128 * PITCHB;       // 10240
constexpr int BUFB   = 2 * ARRB;           // 20480 : A | B
constexpr int PROD_BYTES = 3 * BUFB;       // 61440
constexpr int KCH = 24;
constexpr int NJOBS = T * (XN / 128);      // 6144, 12 per t
constexpr int PITCH = 1040;
constexpr int WSEC  = 32 * PITCH;              // 33280 per gate (32 u rows)
constexpr int W_OFF = PROD_BYTES;              // 61440
constexpr int AHI_OFF = W_OFF + 3 * WSEC;      // 161280
constexpr int ALO_OFF = AHI_OFF + 16 * PITCH;  // 177920
constexpr int SMEM_FUSED = ALO_OFF + 16 * PITCH; // 194560
constexpr int NBLK_BT = 16;
}

__global__ void __launch_bounds__(384, 1) k_fused(const float* __restrict__ gb) {
    extern __shared__ char smem[];
    const uint32_t sb = smem_u32(smem);
    const int tid = threadIdx.x;

    if (tid < 256) {
        // ================= PRODUCTION (1-term fp16) =================
        const int lane = tid & 31, wid = tid >> 5;
        const int wm = wid & 3;
        const int wn = wid >> 2;
        const uint32_t aAddr = sb + (wm * 32 + (lane & 15)) * PITCHB + (lane >> 4) * 16;
        const uint32_t bAddr = sb + ARRB + (wn * 64 + (lane & 15)) * PITCHB + (lane >> 4) * 16;

        for (int job = blockIdx.x; job < NJOBS; job += 128) {
            const int t = job / 12, nt = job % 12;
            const int m0 = t * 128;
            const int n0 = nt * 128;
            const __half* gp0 = g_xh + (size_t)m0 * XK;
            const __half* gp1 = g_bh + (size_t)n0 * XK;

            auto load_chunk = [&](int c, int buf) {
                uint32_t base = sb + buf * BUFB;
#pragma unroll
                for (int l = 0; l < 4; l++) {
                    int idx = tid + 256 * l;
                    int arr = idx >> 9;
                    int rem = idx & 511;
                    int row = rem >> 2;
                    int cch = rem & 3;
                    const __half* g = arr ? gp1 : gp0;
                    cpa16(base + arr * ARRB + row * PITCHB + cch * 16,
                          g + (size_t)row * XK + c * 32 + cch * 8);
                }
                asm volatile("cp.async.commit_group;" ::: "memory");
            };

            float acc[2][8][4];
#pragma unroll
            for (int i = 0; i < 2; i++)
#pragma unroll
                for (int jj = 0; jj < 8; jj++)
#pragma unroll
                    for (int q = 0; q < 4; q++) acc[i][jj][q] = 0.f;

            load_chunk(0, 0);
            load_chunk(1, 1);

            for (int c = 0; c < KCH; c++) {
                if (c + 1 < KCH) asm volatile("cp.async.wait_group 1;" ::: "memory");
                else             asm volatile("cp.async.wait_group 0;" ::: "memory");
                BARNAMED(2, 256);
                if (c + 2 < KCH) load_chunk(c + 2, (c + 2) % 3);

                uint32_t boff = (c % 3) * BUFB;
#pragma unroll
                for (int ks = 0; ks < 2; ks++) {
                    uint32_t ah[2][4], bh[4][4];
#pragma unroll
                    for (int mt = 0; mt < 2; mt++)
                        ldm4(ah[mt], aAddr + boff + mt * (16 * PITCHB) + ks * 32);
#pragma unroll
                    for (int ng = 0; ng < 4; ng++)
                        ldm4(bh[ng], bAddr + boff + ng * (16 * PITCHB) + ks * 32);
#pragma unroll
                    for (int mt = 0; mt < 2; mt++)
#pragma unroll
                        for (int ng = 0; ng < 4; ng++)
#pragma unroll
                            for (int hf = 0; hf < 2; hf++)
                                mma16816(acc[mt][ng * 2 + hf], ah[mt],
                                         bh[ng][hf], bh[ng][hf + 2]);
                }
            }

            const int qr = lane >> 2, qc = lane & 3;
#pragma unroll
            for (int mt = 0; mt < 2; mt++)
#pragma unroll
                for (int ntl = 0; ntl < 8; ntl++) {
                    int nb = n0 + wn * 64 + ntl * 8 + 2 * qc;
                    float b0 = gb[nb], b1 = gb[nb + 1];
#pragma unroll
                    for (int rp = 0; rp < 2; rp++) {
                        int m = m0 + wm * 32 + mt * 16 + qr + 8 * rp;
                        float2 v = make_float2(acc[mt][ntl][2 * rp] + b0,
                                               acc[mt][ntl][2 * rp + 1] + b1);
                        *(float2*)&g_xp[(size_t)m * XN + nb] = v;
                    }
                }

            BARNAMED(2, 256);
            if (tid == 0) atomAddRel(&g_tcnt[t], 1u);
        }
    } else {
        // ================= RECURRENCE (16 b x 32 u per block) =================
        const int ltid = tid - 256;
        const int lane = ltid & 31, lwid = ltid >> 5;  // 4 warps
        const int uh = lwid;
        const int bt = blockIdx.x & 7;
        const int ut = blockIdx.x >> 3;
        const int u0 = ut * 32;
        const int row0 = bt * 16;
        const int qr = lane >> 2, qc = lane & 3;
        const int r1 = row0 + qr;
        const int r2 = r1 + 8;
        const int uc = u0 + uh * 8 + 2 * qc;

        for (int idx = ltid; idx < 6144; idx += 128) {
            int sec = idx >> 11;
            int rem = idx & 2047;
            int r = rem >> 6, ch = rem & 63;
            cpa16(sb + W_OFF + sec * WSEC + r * PITCH + ch * 16,
                  g_rh + ((size_t)(sec * 512 + u0 + r)) * UG + ch * 8);
        }
        asm volatile("cp.async.commit_group;" ::: "memory");

        const float* gbr = gb + XN;
        float bzc[2], brc[2], bhc[2];
#pragma unroll
        for (int j = 0; j < 2; j++) {
            bzc[j] = gbr[uc + j];
            brc[j] = gbr[512 + uc + j];
            bhc[j] = gbr[1024 + uc + j];
        }

        float hprev[4], hmax[4];
        hprev[0] = g_h0f[(size_t)r1 * UG + uc];
        hprev[1] = g_h0f[(size_t)r1 * UG + uc + 1];
        hprev[2] = g_h0f[(size_t)r2 * UG + uc];
        hprev[3] = g_h0f[(size_t)r2 * UG + uc + 1];
#pragma unroll
        for (int i = 0; i < 4; i++) hmax[i] = -INFINITY;

        const uint32_t aHi = sb + AHI_OFF + (lane & 15) * PITCH + ((lane >> 4) & 1) * 16;
        const uint32_t aLo = aHi + 16 * PITCH;
        uint32_t bHi[3];
        {
            int brow = uh * 8 + (lane & 7);
            int bch = lane >> 3;
#pragma unroll
            for (int g = 0; g < 3; g++)
                bHi[g] = sb + W_OFF + g * WSEC + brow * PITCH + bch * 16;
        }

        auto stageA = [&](int par) {
            const __half* shp = g_hh[par] + (size_t)row0 * UG;
            const __half* slp = g_hl[par] + (size_t)row0 * UG;
#pragma unroll
            for (int kh = 0; kh < 2; kh++) {
                for (int idx = ltid; idx < 512; idx += 128) {
                    int r = idx >> 5, ch = (idx & 31) + kh * 32;
                    cpa16(sb + AHI_OFF + r * PITCH + ch * 16, shp + (size_t)r * UG + ch * 8);
                    cpa16(sb + ALO_OFF + r * PITCH + ch * 16, slp + (size_t)r * UG + ch * 8);
                }
                asm volatile("cp.async.commit_group;" ::: "memory");
            }
        };

        stageA(0);

        {
            int spins = 0;
            while (ldAcq(&g_tcnt[0]) < 12u) {
                if (++spins > 16) asm volatile("nanosleep.u32 128;");
            }
        }
        float2 xz[2], xr[2], xh[2];
        {
            const float* xpr1 = g_xp + (size_t)r1 * XN;
            const float* xpr2 = g_xp + (size_t)r2 * XN;
            xz[0] = *(const float2*)(xpr1 + uc);        xz[1] = *(const float2*)(xpr2 + uc);
            xr[0] = *(const float2*)(xpr1 + 512 + uc);  xr[1] = *(const float2*)(xpr2 + 512 + uc);
            xh[0] = *(const float2*)(xpr1 + 1024 + uc); xh[1] = *(const float2*)(xpr2 + 1024 + uc);
        }

        unsigned* barp = &g_barp[bt][0];
        unsigned* genp = &g_genp[bt][0];
        unsigned tdone = 0;   // all timesteps <= tdone have xp produced (monotonic)

        for (int t = 0; t < T; t++) {
            // 8 independent accumulator sets — max chain depth 16
            float az[4] = {0, 0, 0, 0}, azB[4] = {0, 0, 0, 0};
            float ar[4] = {0, 0, 0, 0}, arB[4] = {0, 0, 0, 0};
            float ahA[4] = {0, 0, 0, 0}, ahBv[4] = {0, 0, 0, 0};
            float ahC[4] = {0, 0, 0, 0}, ahD[4] = {0, 0, 0, 0};

            // first k-half
            asm volatile("cp.async.wait_group 1;" ::: "memory");
            BARNAMED(1, 128);
#pragma unroll 4
            for (int j = 0; j < 8; j++) {
                uint32_t ah0[4], ah1[4], al0[4], al1[4];
                uint32_t a = aHi + j * 64;
                ldm4(ah0, a);
                ldm4(ah1, a + 32);
                uint32_t al = aLo + j * 64;
                ldm4(al0, al);
                ldm4(al1, al + 32);
                uint32_t b4h[4];
                ldm4(b4h, bHi[0] + j * 64);
                mma16816(az,  ah0, b4h[0], b4h[1]);
                mma16816(azB, ah1, b4h[2], b4h[3]);
                ldm4(b4h, bHi[1] + j * 64);
                mma16816(ar,  ah0, b4h[0], b4h[1]);
                mma16816(arB, ah1, b4h[2], b4h[3]);
                ldm4(b4h, bHi[2] + j * 64);
                mma16816(ahA,  ah0, b4h[0], b4h[1]);
                mma16816(ahBv, al0, b4h[0], b4h[1]);
                mma16816(ahC,  ah1, b4h[2], b4h[3]);
                mma16816(ahD,  al1, b4h[2], b4h[3]);
            }
            // second k-half
            asm volatile("cp.async.wait_group 0;" ::: "memory");
            BARNAMED(1, 128);
#pragma unroll 4
            for (int j = 8; j < 16; j++) {
                uint32_t ah0[4], ah1[4], al0[4], al1[4];
                uint32_t a = aHi + j * 64;
                ldm4(ah0, a);
                ldm4(ah1, a + 32);
                uint32_t al = aLo + j * 64;
                ldm4(al0, al);
                ldm4(al1, al + 32);
                uint32_t b4h[4];
                ldm4(b4h, bHi[0] + j * 64);
                mma16816(az,  ah0, b4h[0], b4h[1]);
                mma16816(azB, ah1, b4h[2], b4h[3]);
                ldm4(b4h, bHi[1] + j * 64);
                mma16816(ar,  ah0, b4h[0], b4h[1]);
                mma16816(arB, ah1, b4h[2], b4h[3]);
                ldm4(b4h, bHi[2] + j * 64);
                mma16816(ahA,  ah0, b4h[0], b4h[1]);
                mma16816(ahBv, al0, b4h[0], b4h[1]);
                mma16816(ahC,  ah1, b4h[2], b4h[3]);
                mma16816(ahD,  al1, b4h[2], b4h[3]);
            }

#pragma unroll
            for (int i = 0; i < 4; i++) {
                az[i] += azB[i];
                ar[i] += arB[i];
                ahA[i] = (ahA[i] + ahBv[i]) + (ahC[i] + ahD[i]);
            }

            int np = (t + 1) & 1;
            bool notlast = (t + 1 < T);
#pragma unroll
            for (int pp = 0; pp < 2; pp++) {
                float hn[2];
#pragma unroll
                for (int j = 0; j < 2; j++) {
                    int i = 2 * pp + j;
                    float xzv = j ? xz[pp].y : xz[pp].x;
                    float xrv = j ? xr[pp].y : xr[pp].x;
                    float xhv = j ? xh[pp].y : xh[pp].x;
                    float z = fsigm(xzv + az[i] + bzc[j]);
                    float r = fsigm(xrv + ar[i] + brc[j]);
                    float hc = ftanh(xhv + r * (ahA[i] + bhc[j]));
                    hn[j] = z * hprev[i] + (1.f - z) * hc;
                    hprev[i] = hn[j];
                    hmax[i] = fmaxf(hmax[i], hn[j]);
                }
                if (notlast) {
                    int rowg = pp ? r2 : r1;
                    __half2 vh, vl;
                    __half h0b, l0b, h1b, l1b;
                    split_f16(hn[0], h0b, l0b);
                    split_f16(hn[1], h1b, l1b);
                    vh.x = h0b; vh.y = h1b;
                    vl.x = l0b; vl.y = l1b;
                    *(__half2*)&g_hh[np][(size_t)rowg * UG + uc] = vh;
                    *(__half2*)&g_hl[np][(size_t)rowg * UG + uc] = vl;
                }
            }

            if (notlast) {
                // EARLY ARRIVE: publish h before local prefetch work
                BARNAMED(1, 128);
                if (ltid == 0) {
                    unsigned target = (unsigned)(t + 1) * NBLK_BT;
                    unsigned old = atomAddRel(barp, 1);
                    if (old == target - 1) stRel(genp, (unsigned)(t + 1));
                }
                // xp(t+1) readiness: poll only when not already known-produced.
                // Production is t-major + tcnt monotonic -> probe ahead to skip
                // future polls (removes one L2 round-trip/step in steady state).
                if ((unsigned)(t + 1) > tdone) {
                    int spins = 0;
                    while (ldAcq(&g_tcnt[t + 1]) < 12u) {
                        if (++spins > 16) asm volatile("nanosleep.u32 128;");
                    }
                    int ahead = t + 32;
                    if (ahead > T - 1) ahead = T - 1;
                    tdone = (ldAcq(&g_tcnt[ahead]) >= 12u) ? (unsigned)ahead
                                                           : (unsigned)(t + 1);
                }
                {
                    const float* xp = g_xp + (size_t)(t + 1) * ((size_t)B * XN);
                    const float* xpr1 = xp + (size_t)r1 * XN;
                    const float* xpr2 = xp + (size_t)r2 * XN;
                    xz[0] = *(const float2*)(xpr1 + uc);        xz[1] = *(const float2*)(xpr2 + uc);
                    xr[0] = *(const float2*)(xpr1 + 512 + uc);  xr[1] = *(const float2*)(xpr2 + 512 + uc);
                    xh[0] = *(const float2*)(xpr1 + 1024 + uc); xh[1] = *(const float2*)(xpr2 + 1024 + uc);
                }
                {
                    int spins = 0;
                    while (ldAcq(genp) < (unsigned)(t + 1)) {
                        if (++spins > 64) asm volatile("nanosleep.u32 32;");
                    }
                }
                stageA(np);
            }
        }

        float2 v;
        v.x = hmax[0]; v.y = hmax[1]; *(float2*)&g_hmax[(size_t)r1 * UG + uc] = v;
        v.x = hmax[2]; v.y = hmax[3]; *(float2*)&g_hmax[(size_t)r2 * UG + uc] = v;
        v.x = hprev[0]; v.y = hprev[1]; *(float2*)&g_h0f[(size_t)r1 * UG + uc] = v;
        v.x = hprev[2]; v.y = hprev[3]; *(float2*)&g_h0f[(size_t)r2 * UG + uc] = v;
    }
}

// ---------------- epilogue ---------------------------------------------------
__global__ void k_out(const float* __restrict__ Wout, const float* __restrict__ bout,
                      float* __restrict__ dout, int out_size) {
    int b = blockIdx.x;
    int tid = threadIdx.x; // 256
    __shared__ float red[256];
    float s = 0.f;
    for (int uu = tid; uu < UG; uu += 256) s += g_hmax[b * UG + uu] * Wout[uu];
    red[tid] = s;
    __syncthreads();
    for (int o = 128; o > 0; o >>= 1) {
        if (tid < o) red[tid] += red[tid + o];
        __syncthreads();
    }
    if (tid == 0 && b < out_size) dout[b] = eluf(red[0] + bout[0]);
    for (int uu = tid; uu < UG; uu += 256) {
        int idx = B + b * UG + uu;
        if (idx < out_size) dout[idx] = g_h0f[b * UG + uu];
    }
}

// ---------------- launch ------------------------------------------------------
extern "C" void kernel_launch(void* const* d_in, const int* in_sizes, int n_in,
                              void* d_out, int out_size) {
    const float* motion = (const float*)d_in[0];
    const float* robot  = (const float*)d_in[1];
    const float* action = (const float*)d_in[3];
    const float* osc    = (const float*)d_in[4];
    const float* mu     = (const float*)d_in[5];
    const float* mean   = (const float*)d_in[6];
    const float* state  = (const float*)d_in[7];
    const float* W_mot  = (const float*)d_in[8];
    const float* b_mot  = (const float*)d_in[9];
    const float* W_rob  = (const float*)d_in[10];
    const float* b_rob  = (const float*)d_in[11];
    const float* W_comb = (const float*)d_in[12];
    const float* b_comb = (const float*)d_in[13];
    const float* W_oscr = (const float*)d_in[14];
    const float* b_oscr = (const float*)d_in[15];
    const float* W_osci = (const float*)d_in[16];
    const float* b_osci = (const float*)d_in[17];
    const float* gru_k  = (const float*)d_in[18];
    const float* gru_rk = (const float*)d_in[19];
    const float* gru_b  = (const float*)d_in[20];
    const float* W_out  = (const float*)d_in[21];
    const float* b_out  = (const float*)d_in[22];
    float* out = (float*)d_out;

    static bool attr_set = false;
    if (!attr_set) {
        cudaFuncSetAttribute(k_fused, cudaFuncAttributeMaxDynamicSharedMemorySize, SMEM_FUSED);
        attr_set = true;
    }

    k_reset<<<1, 512>>>();                                             // 0
    k_init<<<B, 512>>>(motion, robot, state, W_mot, b_mot,
                       W_rob, b_rob, W_comb, b_comb);                  // 1
    k_front<<<ROWS / 8, 256>>>(action, mu, mean, osc,
                               W_oscr, b_oscr, W_osci, b_osci);        // 2
    k_trb<<<dim3(XN / 32, XK / 32), dim3(32, 8)>>>(gru_k);             // 3
    k_trw<<<dim3(XN / 32, UG / 32), dim3(32, 8)>>>(gru_rk);            // 4
    k_fused<<<128, 384, SMEM_FUSED>>>(gru_b);                          // 5
    k_out<<<B, 256>>>(W_out, b_out, out, out_size);                    // 6
}